// round 16
// baseline (speedup 1.0000x reference)
#include <cuda_runtime.h>
#include <cuda_bf16.h>
#include <cuda_fp16.h>
#include <cstdint>

#define NN 100000
#define NE 1600000
#define NSCAN 98   // (NN + 1023) / 1024

// ---------------- scratch (__device__ globals; allocations are forbidden) ----------------
// Zero-initialized at module load; kernels restore the zero-state of
// g_cnt / g_colsum / g_sumsq / g_nlraw / g_scnt / g_flag at the end of every call.
__device__ __align__(256) __half g_xg16[NN * 128];
__device__ __align__(256) __half g_hemb[NN * 128];
__device__ __align__(256) __half g_q16 [NN * 32];
__device__ __align__(256) __half g_y16 [NN * 32];
__device__ __align__(256) __half g_h16 [NN * 128];
__device__ __align__(256) __half g_x16 [NN * 128];
__device__ __align__(256) __half g_xd16[NN * 128];
__device__ __align__(256) __half g_t2  [NN * 128];
__device__ __align__(256) __half g_h2  [NN * 192];
__device__ __align__(256) __half g_w16 [NN * 32];
__device__ __align__(256) float  g_sumsq[NN];
__device__ __align__(256) float  g_s   [NN];
__device__ float g_colsum[128];
__device__ float g_small[80];           // z[0..63], sum(z^2) at [64]
__device__ float g_v[192];              // z @ Wh2[128:192, :]
// packed fp16 weights: Wp[k2*DOUT+n] = half2(W[2k2][n], W[2k2+1][n])
__device__ __align__(256) uint32_t g_Wxhp[64 * 128];
__device__ __align__(256) uint32_t g_Wg1p[64 * 128];
__device__ __align__(256) uint32_t g_Wg2p[64 * 32];
__device__ __align__(256) uint32_t g_Wxyp[80 * 128];
__device__ __align__(256) uint32_t g_Wh2p[64 * 192];   // only k-rows 0..127
__device__ __align__(256) uint32_t g_Whyp[96 * 32];
__device__ int   g_rowptr[NN + 1];
__device__ int   g_cnt[NN + 1];
__device__ int   g_wpos[NN];
__device__ int   g_bsum[128];
__device__ int   g_bpref[128];
__device__ int   g_scnt;
__device__ int   g_flag;
__device__ __align__(256) int2 g_cw[NE];   // packed (col, weight-bits)
__device__ int   g_nlraw;

// ---------------- MEGA1: hist + cvt_xd + weight-pack + detect_nl ----------------
__device__ __forceinline__ void wp_seg(const float* __restrict__ W, uint32_t* __restrict__ Wp,
                                       int idx, int DOUT) {
    int k2 = idx / DOUT, n = idx % DOUT;
    __half2 h = __floats2half2_rn(__ldg(W + (size_t)(2 * k2) * DOUT + n),
                                  __ldg(W + (size_t)(2 * k2 + 1) * DOUT + n));
    Wp[idx] = *reinterpret_cast<uint32_t*>(&h);
}

#define MEGA1_HB 6250
#define MEGA1_CB 12500
#define MEGA1_WB 172
#define MEGA1_DB 98
#define MEGA1_GRID (MEGA1_HB + MEGA1_CB + MEGA1_WB + MEGA1_DB)

__global__ void __launch_bounds__(256) mega1_kernel(const int* __restrict__ ei,
                                                    const float* __restrict__ x,
                                                    const float* __restrict__ dm,
                                                    const float* __restrict__ Wxh,
                                                    const float* __restrict__ Wg1,
                                                    const float* __restrict__ Wg2,
                                                    const float* __restrict__ Wxy,
                                                    const float* __restrict__ Wh2,
                                                    const float* __restrict__ Why,
                                                    const unsigned* __restrict__ nl) {
    int bid = blockIdx.x, tid = threadIdx.x;
    if (bid < MEGA1_HB) {                       // histogram
        int e = bid * 256 + tid;
        if (e < NE) atomicAdd(&g_cnt[ei[e]], 1);
        return;
    }
    bid -= MEGA1_HB;
    if (bid < MEGA1_CB) {                       // x / x*dmask -> fp16
        int i = bid * 256 + tid;
        float4 v = __ldg(reinterpret_cast<const float4*>(x) + i);
        float4 m = __ldg(reinterpret_cast<const float4*>(dm) + i);
        __half2 a = __floats2half2_rn(v.x, v.y);
        __half2 b = __floats2half2_rn(v.z, v.w);
        uint2 o;
        o.x = *reinterpret_cast<uint32_t*>(&a);
        o.y = *reinterpret_cast<uint32_t*>(&b);
        reinterpret_cast<uint2*>(g_x16)[i] = o;
        __half2 c = __floats2half2_rn(v.x * m.x, v.y * m.y);
        __half2 d = __floats2half2_rn(v.z * m.z, v.w * m.w);
        uint2 od;
        od.x = *reinterpret_cast<uint32_t*>(&c);
        od.y = *reinterpret_cast<uint32_t*>(&d);
        reinterpret_cast<uint2*>(g_xd16)[i] = od;
        return;
    }
    bid -= MEGA1_CB;
    if (bid < MEGA1_WB) {                       // weight packing, 6 segments
        int i = bid * 256 + tid;
        if (i < 8192)       wp_seg(Wxh, g_Wxhp, i, 128);
        else if (i < 16384) wp_seg(Wg1, g_Wg1p, i - 8192, 128);
        else if (i < 18432) wp_seg(Wg2, g_Wg2p, i - 16384, 32);
        else if (i < 28672) wp_seg(Wxy, g_Wxyp, i - 18432, 128);
        else if (i < 40960) wp_seg(Wh2, g_Wh2p, i - 28672, 192);
        else if (i < 44032) wp_seg(Why, g_Whyp, i - 40960, 32);
        return;
    }
    bid -= MEGA1_WB;
    {                                           // non_label dtype detect
        int i = bid * 256 + tid;
        int f = 0;
        if (i < NN / 4) {
            unsigned v = nl[i];
            if (v == 0x00003F80u || v == 0x3F803F80u) f = 4;
            else if (v == 0x3F800000u) f = 2;
            else if (v > 1u) f = 1;
        }
        if (f) atomicOr(&g_nlraw, f);
    }
}

// ---------------- CSR scan (single kernel; all 98 blocks wave-1 resident) ----------------
__global__ void __launch_bounds__(1024) scan_all() {
    __shared__ int wsum[32];
    __shared__ int pr[128];
    __shared__ int slast;
    int tid = threadIdx.x;
    int lane = tid & 31, wid = tid >> 5;
    int i = blockIdx.x * 1024 + tid;
    int v = (i < NN) ? g_cnt[i] : 0;
    if (i < NN) g_cnt[i] = 0;                 // restore for next call
    int xv = v;
#pragma unroll
    for (int o = 1; o < 32; o <<= 1) {
        int t = __shfl_up_sync(0xffffffffu, xv, o);
        if (lane >= o) xv += t;
    }
    if (lane == 31) wsum[wid] = xv;
    __syncthreads();
    if (wid == 0) {
        int w = wsum[lane];
#pragma unroll
        for (int o = 1; o < 32; o <<= 1) {
            int t = __shfl_up_sync(0xffffffffu, w, o);
            if (lane >= o) w += t;
        }
        wsum[lane] = w;
    }
    __syncthreads();
    int incl = xv + (wid ? wsum[wid - 1] : 0);
    if (tid == 1023) {
        g_bsum[blockIdx.x] = incl;
        __threadfence();
        int old = atomicAdd(&g_scnt, 1);
        slast = (old == NSCAN - 1);
    }
    __syncthreads();
    if (slast) {                               // block-uniform branch
        __threadfence();
        if (tid < 128) pr[tid] = (tid < NSCAN) ? ((volatile int*)g_bsum)[tid] : 0;
        __syncthreads();
#pragma unroll
        for (int o = 1; o < 128; o <<= 1) {
            int t = (tid < 128 && tid >= o) ? pr[tid - o] : 0;
            __syncthreads();
            if (tid < 128) pr[tid] += t;
            __syncthreads();
        }
        if (tid < NSCAN) g_bpref[tid] = tid ? pr[tid - 1] : 0;   // exclusive
        __threadfence();
        if (tid == 0) atomicExch(&g_flag, 1);
        __syncthreads();
    } else {
        if (tid == 0) { while (atomicAdd(&g_flag, 0) == 0) {} }
        __syncthreads();
        __threadfence();
    }
    int ex = incl - v + g_bpref[blockIdx.x];
    if (i < NN) {
        g_rowptr[i] = ex;
        g_wpos[i] = ex;
    }
    if (i == 0) g_rowptr[NN] = NE;
}

// ---------------- SPMM: warp per row, atomic-free ----------------
// BR: fuse out = relu(acc + bias) (D=128 fp16 path only). D=128 loop is 2x-unrolled
// (clean step-2 loop + remainder; edge order and fp math identical to rolled form).
template<int D, typename T, typename OT, bool BR>
__global__ void __launch_bounds__(256) spmm_kernel(const T* __restrict__ h,
                                                   OT* __restrict__ out,
                                                   const float* __restrict__ bias) {
    int row = (blockIdx.x * blockDim.x + threadIdx.x) >> 5;
    if (row >= NN) return;
    int lane = threadIdx.x & 31;
    int s = g_rowptr[row], e = g_rowptr[row + 1];

    if constexpr (D == 32) {
        float acc = 0.f;
        for (; s < e; ++s) {
            int2 cw = __ldg(&g_cw[s]);
            float w = __int_as_float(cw.y);
            float v;
            if constexpr (sizeof(T) == 2) v = __half2float(__ldg((const __half*)h + (size_t)cw.x * 32 + lane));
            else                          v = __ldg((const float*)h + (size_t)cw.x * 32 + lane);
            acc = fmaf(w, v, acc);
        }
        ((float*)out)[(size_t)row * 32 + lane] = acc + (bias ? bias[lane] : 0.f);
    } else { // D == 128, fp16 -> fp16, 2x unrolled
        float4 a = make_float4(0.f, 0.f, 0.f, 0.f);
        for (; s + 2 <= e; s += 2) {
            int2 c0 = __ldg(&g_cw[s]);
            int2 c1 = __ldg(&g_cw[s + 1]);
            uint2 r0 = __ldg(reinterpret_cast<const uint2*>((const __half*)h + (size_t)c0.x * 128) + lane);
            uint2 r1 = __ldg(reinterpret_cast<const uint2*>((const __half*)h + (size_t)c1.x * 128) + lane);
            float w0 = __int_as_float(c0.y);
            float2 f0 = __half22float2(*reinterpret_cast<__half2*>(&r0.x));
            float2 f1 = __half22float2(*reinterpret_cast<__half2*>(&r0.y));
            a.x = fmaf(w0, f0.x, a.x); a.y = fmaf(w0, f0.y, a.y);
            a.z = fmaf(w0, f1.x, a.z); a.w = fmaf(w0, f1.y, a.w);
            float w1 = __int_as_float(c1.y);
            float2 g0 = __half22float2(*reinterpret_cast<__half2*>(&r1.x));
            float2 g1 = __half22float2(*reinterpret_cast<__half2*>(&r1.y));
            a.x = fmaf(w1, g0.x, a.x); a.y = fmaf(w1, g0.y, a.y);
            a.z = fmaf(w1, g1.x, a.z); a.w = fmaf(w1, g1.y, a.w);
        }
        if (s < e) {
            int2 cw = __ldg(&g_cw[s]);
            float w = __int_as_float(cw.y);
            uint2 raw = __ldg(reinterpret_cast<const uint2*>((const __half*)h + (size_t)cw.x * 128) + lane);
            float2 f0 = __half22float2(*reinterpret_cast<__half2*>(&raw.x));
            float2 f1 = __half22float2(*reinterpret_cast<__half2*>(&raw.y));
            a.x = fmaf(w, f0.x, a.x); a.y = fmaf(w, f0.y, a.y);
            a.z = fmaf(w, f1.x, a.z); a.w = fmaf(w, f1.y, a.w);
        }
        if constexpr (BR) {
            float4 b = __ldg(reinterpret_cast<const float4*>(bias) + lane);
            a.x = fmaxf(a.x + b.x, 0.f); a.y = fmaxf(a.y + b.y, 0.f);
            a.z = fmaxf(a.z + b.z, 0.f); a.w = fmaxf(a.w + b.w, 0.f);
        }
        __half2 o0 = __floats2half2_rn(a.x, a.y);
        __half2 o1 = __floats2half2_rn(a.z, a.w);
        uint2 ov;
        ov.x = *reinterpret_cast<uint32_t*>(&o0);
        ov.y = *reinterpret_cast<uint32_t*>(&o1);
        reinterpret_cast<uint2*>((__half*)out + (size_t)row * 128)[lane] = ov;
    }
}

// SPMM D=128 over UNNORMALIZED h16, per-edge inv = rsqrt(sumsq+|z|^2), rank-1 scalar channel
// 2x-unrolled like spmm_kernel<128>.
__global__ void __launch_bounds__(256) spmm128s_kernel(const __half* __restrict__ h,
                                                       __half* __restrict__ out) {
    int row = (blockIdx.x * blockDim.x + threadIdx.x) >> 5;
    if (row >= NN) return;
    int lane = threadIdx.x & 31;
    float sz = g_small[64];
    int s = g_rowptr[row], e = g_rowptr[row + 1];
    float4 a = make_float4(0.f, 0.f, 0.f, 0.f);
    float sacc = 0.f;
    for (; s + 2 <= e; s += 2) {
        int2 c0 = __ldg(&g_cw[s]);
        int2 c1 = __ldg(&g_cw[s + 1]);
        float q0 = __ldg(g_sumsq + c0.x);
        float q1 = __ldg(g_sumsq + c1.x);
        uint2 r0 = __ldg(reinterpret_cast<const uint2*>(h + (size_t)c0.x * 128) + lane);
        uint2 r1 = __ldg(reinterpret_cast<const uint2*>(h + (size_t)c1.x * 128) + lane);
        float w0 = __int_as_float(c0.y) * rsqrtf(q0 + sz);
        sacc += w0;
        float2 f0 = __half22float2(*reinterpret_cast<__half2*>(&r0.x));
        float2 f1 = __half22float2(*reinterpret_cast<__half2*>(&r0.y));
        a.x = fmaf(w0, f0.x, a.x); a.y = fmaf(w0, f0.y, a.y);
        a.z = fmaf(w0, f1.x, a.z); a.w = fmaf(w0, f1.y, a.w);
        float w1 = __int_as_float(c1.y) * rsqrtf(q1 + sz);
        sacc += w1;
        float2 g0 = __half22float2(*reinterpret_cast<__half2*>(&r1.x));
        float2 g1 = __half22float2(*reinterpret_cast<__half2*>(&r1.y));
        a.x = fmaf(w1, g0.x, a.x); a.y = fmaf(w1, g0.y, a.y);
        a.z = fmaf(w1, g1.x, a.z); a.w = fmaf(w1, g1.y, a.w);
    }
    if (s < e) {
        int2 cw = __ldg(&g_cw[s]);
        float wi = __int_as_float(cw.y) * rsqrtf(__ldg(g_sumsq + cw.x) + sz);
        uint2 raw = __ldg(reinterpret_cast<const uint2*>(h + (size_t)cw.x * 128) + lane);
        sacc += wi;
        float2 f0 = __half22float2(*reinterpret_cast<__half2*>(&raw.x));
        float2 f1 = __half22float2(*reinterpret_cast<__half2*>(&raw.y));
        a.x = fmaf(wi, f0.x, a.x); a.y = fmaf(wi, f0.y, a.y);
        a.z = fmaf(wi, f1.x, a.z); a.w = fmaf(wi, f1.y, a.w);
    }
    __half2 o0 = __floats2half2_rn(a.x, a.y);
    __half2 o1 = __floats2half2_rn(a.z, a.w);
    uint2 ov;
    ov.x = *reinterpret_cast<uint32_t*>(&o0);
    ov.y = *reinterpret_cast<uint32_t*>(&o1);
    reinterpret_cast<uint2*>(out + (size_t)row * 128)[lane] = ov;
    if (lane == 0) g_s[row] = sacc;
}

// SPMM D=32 over q16 fused with gumbel softmax(hard) + label select -> g_y16
__global__ void __launch_bounds__(256) spmm_gumbel_kernel(const __half* __restrict__ q16,
                                                          const float* __restrict__ bg2,
                                                          const float* __restrict__ ug,
                                                          const float* __restrict__ ylab,
                                                          const void* __restrict__ nl) {
    int row = (blockIdx.x * blockDim.x + threadIdx.x) >> 5;
    if (row >= NN) return;
    int lane = threadIdx.x & 31;
    int s = g_rowptr[row], e = g_rowptr[row + 1];
    float acc = 0.f;
    for (; s < e; ++s) {
        int2 cw = __ldg(&g_cw[s]);
        acc = fmaf(__int_as_float(cw.y),
                   __half2float(__ldg(q16 + (size_t)cw.x * 32 + lane)), acc);
    }
    float l = acc + __ldg(bg2 + lane);
    float u = __ldg(ug + (size_t)row * 32 + lane);
    float gg = -logf(-logf(u + 1e-10f) + 1e-10f);
    float t = l + gg;
    float m = t;
#pragma unroll
    for (int o = 16; o; o >>= 1) m = fmaxf(m, __shfl_xor_sync(0xffffffffu, m, o));
    unsigned ball = __ballot_sync(0xffffffffu, t == m);
    int amax = __ffs(ball) - 1;
    float ex = expf(t - m);
    float ssum = ex;
#pragma unroll
    for (int o = 16; o; o >>= 1) ssum += __shfl_xor_sync(0xffffffffu, ssum, o);
    float soft = ex / ssum;
    float hard = (lane == amax) ? 1.f : 0.f;
    float ygum = (hard + soft) - soft;
    int raw = g_nlraw;
    bool isnl;
    if (raw & 4)      isnl = __bfloat162float(((const __nv_bfloat16*)nl)[row]) != 0.f;
    else if (raw & 2) isnl = ((const float*)nl)[row] != 0.f;
    else if (raw & 1) isnl = ((const unsigned char*)nl)[row] != 0;
    else              isnl = ((const int*)nl)[row] != 0;
    g_y16[row * 32 + lane] = __float2half(isnl ? ygum : __ldg(ylab + (size_t)row * 32 + lane));
}

// Final SPMM D=32 -> d_out, trailing blocks restore g_sumsq / g_nlraw / g_scnt / g_flag
__global__ void __launch_bounds__(256) spmm32_final_kernel(const __half* __restrict__ h,
                                                           float* __restrict__ out,
                                                           const float* __restrict__ bias) {
    const int SPB = (NN * 32) / 256;   // 12500 spmm blocks
    if (blockIdx.x >= SPB) {
        int zi = (blockIdx.x - SPB) * 256 + threadIdx.x;
        if (zi < NN) g_sumsq[zi] = 0.f;
        if (zi == 0) { g_nlraw = 0; g_scnt = 0; g_flag = 0; }
        return;
    }
    int row = (blockIdx.x * blockDim.x + threadIdx.x) >> 5;
    if (row >= NN) return;
    int lane = threadIdx.x & 31;
    int s = g_rowptr[row], e = g_rowptr[row + 1];
    float acc = 0.f;
    for (; s < e; ++s) {
        int2 cw = __ldg(&g_cw[s]);
        acc = fmaf(__int_as_float(cw.y),
                   __half2float(__ldg(h + (size_t)cw.x * 32 + lane)), acc);
    }
    out[(size_t)row * 32 + lane] = acc + __ldg(bias + lane);
}

// ---------------- tensor-core GEMM (full-W preload, per-warp A pipeline) ----------------
__device__ __forceinline__ void mma_f16(float* d, const uint32_t* a, const uint32_t* b) {
    asm volatile(
        "mma.sync.aligned.m16n8k16.row.col.f32.f16.f16.f32 "
        "{%0,%1,%2,%3},{%4,%5,%6,%7},{%8,%9},{%0,%1,%2,%3};"
        : "+f"(d[0]), "+f"(d[1]), "+f"(d[2]), "+f"(d[3])
        : "r"(a[0]), "r"(a[1]), "r"(a[2]), "r"(a[3]), "r"(b[0]), "r"(b[1]));
}
__device__ __forceinline__ void cpa16(uint32_t dst, const void* src, int sz) {
    asm volatile("cp.async.ca.shared.global [%0], [%1], 16, %2;" :: "r"(dst), "l"(src), "r"(sz));
}

// MODE 0: C = act(A1 @ W + b); MODE 1: relu + column sums (A=[A1 128 | A2 32]);
// MODE 2: MODE 0 + row sum-of-squares atomics
// RANK1: acc += g_s[row]*g_v[col] before bias/relu
// SCAT:  block ranges = [primary GEMM | secondary GEMM (A1b@Wgb->C16b plain) | edge scatter]
template<int DIN, int DOUT, int BN, int MODE, bool RELU, bool RANK1, bool W32, bool W16, bool SCAT>
__global__ void __launch_bounds__(256) gemm_tc(const __half* __restrict__ A1,
                                               const __half* __restrict__ A2,
                                               const uint32_t* __restrict__ Wg,
                                               const float* __restrict__ bias,
                                               float* __restrict__ C,
                                               __half* __restrict__ C16,
                                               const int* __restrict__ ei,
                                               const float* __restrict__ ew,
                                               const __half* __restrict__ A1b,
                                               const uint32_t* __restrict__ Wgb,
                                               __half* __restrict__ C16b) {
    constexpr int GMc = (NN + 127) / 128;
    constexpr int KC = 32;
    constexpr int AST2 = 20;
    constexpr int WST = BN + 8;
    constexpr int NT = BN / 8;
    constexpr int NCH = DIN / KC;
    constexpr int NK2 = DIN / 2;

    const int tid = threadIdx.x;
    int bx, by;
    bool sec = false;
    if constexpr (SCAT) {
        constexpr int GB = GMc * (DOUT / BN);
        if (blockIdx.x >= 2 * GB) {
            int e = (blockIdx.x - 2 * GB) * 256 + tid;
            if (e < NE) {
                int r = __ldg(ei + e);
                int p = atomicAdd(&g_wpos[r], 1);
                g_cw[p] = make_int2(__ldg(ei + NE + e), __float_as_int(__ldg(ew + e)));
            }
            return;
        }
        int b = blockIdx.x;
        if (b >= GB) { sec = true; b -= GB; }
        bx = b % GMc;
        by = b / GMc;
    } else {
        bx = blockIdx.x;
        by = blockIdx.y;
    }

    __shared__ uint32_t As2[2][128][AST2];
    __shared__ uint32_t Ws[NK2][WST];
    __shared__ float s_cs[(MODE == 1) ? BN : 1];

    const int wid  = tid >> 5;
    const int lane = tid & 31;
    const int row0 = bx * 128;
    const int n0   = by * BN;

    const __half* Ap = (SCAT && sec) ? A1b : A1;
    const uint32_t* Wp = (SCAT && sec) ? Wgb : Wg;

    if constexpr (MODE == 1) { if (tid < BN) s_cs[tid] = 0.f; }

    constexpr int W4 = NK2 * (BN / 4);
    for (int i = tid; i < W4; i += 256) {
        int k2 = i / (BN / 4);
        int c4 = (i % (BN / 4)) * 4;
        cpa16((uint32_t)__cvta_generic_to_shared(&Ws[k2][c4]),
              Wp + (size_t)k2 * DOUT + n0 + c4, 16);
    }
    asm volatile("cp.async.commit_group;");

    auto load_A = [&](int buf, int kc) {
#pragma unroll
        for (int j = 0; j < 2; j++) {
            int sid = lane + j * 32;
            int r = wid * 16 + (sid >> 2);
            int seg = sid & 3;
            int gr = row0 + r;
            int sz = (gr < NN) ? 16 : 0;
            int grc = (gr < NN) ? gr : (NN - 1);
            int gk = kc + seg * 8;
            const __half* src;
            if constexpr (MODE == 1) {
                src = (gk < 128) ? (Ap + (size_t)grc * 128 + gk)
                                 : (A2 + (size_t)grc * 32 + (gk - 128));
            } else {
                src = Ap + (size_t)grc * DIN + gk;
            }
            cpa16((uint32_t)__cvta_generic_to_shared(&As2[buf][r][seg * 4]), src, sz);
        }
        asm volatile("cp.async.commit_group;");
    };

    float acc[NT][4];
#pragma unroll
    for (int t = 0; t < NT; t++)
#pragma unroll
        for (int j = 0; j < 4; j++) acc[t][j] = 0.f;

    load_A(0, 0);
    asm volatile("cp.async.wait_group 1;");
    __syncthreads();

#pragma unroll
    for (int c = 0; c < NCH; c++) {
        if (c + 1 < NCH) {
            load_A((c + 1) & 1, (c + 1) * KC);
            asm volatile("cp.async.wait_group 1;");
        } else {
            asm volatile("cp.async.wait_group 0;");
        }
        __syncwarp();
        const int buf = c & 1;
#pragma unroll
        for (int s = 0; s < 2; s++) {
            int k2o = s * 8;
            int m0 = wid * 16;
            int r = lane >> 2, q = lane & 3, bp = lane >> 2;
            uint32_t a[4];
            a[0] = As2[buf][m0 + r][k2o + q];
            a[1] = As2[buf][m0 + r + 8][k2o + q];
            a[2] = As2[buf][m0 + r][k2o + 4 + q];
            a[3] = As2[buf][m0 + r + 8][k2o + 4 + q];
#pragma unroll
            for (int t = 0; t < NT; t++) {
                uint32_t b[2];
                b[0] = Ws[c * 16 + k2o + q][t * 8 + bp];
                b[1] = Ws[c * 16 + k2o + 4 + q][t * 8 + bp];
                mma_f16(acc[t], a, b);
            }
        }
    }

    const int er0 = row0 + wid * 16 + (lane >> 2);
    const int er1 = er0 + 8;

    if (SCAT && sec) {     // secondary GEMM: plain fp16 store, no bias/relu
#pragma unroll
        for (int t = 0; t < NT; t++) {
            int gc = n0 + t * 8 + 2 * (lane & 3);
            if (er0 < NN)
                *reinterpret_cast<__half2*>(&C16b[(size_t)er0 * DOUT + gc]) =
                    __floats2half2_rn(acc[t][0], acc[t][1]);
            if (er1 < NN)
                *reinterpret_cast<__half2*>(&C16b[(size_t)er1 * DOUT + gc]) =
                    __floats2half2_rn(acc[t][2], acc[t][3]);
        }
        return;
    }

    if constexpr (MODE == 1) {
#pragma unroll
        for (int t = 0; t < NT; t++) {
            int gc = n0 + t * 8 + 2 * (lane & 3);
            float b0 = __ldg(bias + gc), b1 = __ldg(bias + gc + 1);
            float v0 = 0.f, v1 = 0.f;
            if (er0 < NN) { v0 += fmaxf(acc[t][0] + b0, 0.f); v1 += fmaxf(acc[t][1] + b1, 0.f); }
            if (er1 < NN) { v0 += fmaxf(acc[t][2] + b0, 0.f); v1 += fmaxf(acc[t][3] + b1, 0.f); }
#pragma unroll
            for (int o = 4; o < 32; o <<= 1) {
                v0 += __shfl_xor_sync(0xffffffffu, v0, o);
                v1 += __shfl_xor_sync(0xffffffffu, v1, o);
            }
            if ((lane >> 2) == 0) {
                atomicAdd(&s_cs[t * 8 + 2 * (lane & 3)], v0);
                atomicAdd(&s_cs[t * 8 + 2 * (lane & 3) + 1], v1);
            }
        }
        __syncthreads();
        if (tid < BN) atomicAdd(&g_colsum[n0 + tid], s_cs[tid]);
    } else {
        float s0 = 0.f, s1 = 0.f;
        if constexpr (RANK1) {
            if (er0 < NN) s0 = __ldg(g_s + er0);
            if (er1 < NN) s1 = __ldg(g_s + er1);
        }
        float ss0 = 0.f, ss1 = 0.f;
#pragma unroll
        for (int t = 0; t < NT; t++) {
            int gc = n0 + t * 8 + 2 * (lane & 3);
            float b0 = bias ? __ldg(bias + gc) : 0.f;
            float b1 = bias ? __ldg(bias + gc + 1) : 0.f;
            float2 o0 = make_float2(acc[t][0] + b0, acc[t][1] + b1);
            float2 o1 = make_float2(acc[t][2] + b0, acc[t][3] + b1);
            if constexpr (RANK1) {
                float v0 = __ldg(g_v + gc), v1 = __ldg(g_v + gc + 1);
                o0.x = fmaf(s0, v0, o0.x); o0.y = fmaf(s0, v1, o0.y);
                o1.x = fmaf(s1, v0, o1.x); o1.y = fmaf(s1, v1, o1.y);
            }
            if (RELU) {
                o0.x = fmaxf(o0.x, 0.f); o0.y = fmaxf(o0.y, 0.f);
                o1.x = fmaxf(o1.x, 0.f); o1.y = fmaxf(o1.y, 0.f);
            }
            if constexpr (MODE == 2) {
                ss0 = fmaf(o0.x, o0.x, fmaf(o0.y, o0.y, ss0));
                ss1 = fmaf(o1.x, o1.x, fmaf(o1.y, o1.y, ss1));
            }
            if (er0 < NN) {
                if (W32) *reinterpret_cast<float2*>(&C[(size_t)er0 * DOUT + gc]) = o0;
                if (W16) *reinterpret_cast<__half2*>(&C16[(size_t)er0 * DOUT + gc]) = __floats2half2_rn(o0.x, o0.y);
            }
            if (er1 < NN) {
                if (W32) *reinterpret_cast<float2*>(&C[(size_t)er1 * DOUT + gc]) = o1;
                if (W16) *reinterpret_cast<__half2*>(&C16[(size_t)er1 * DOUT + gc]) = __floats2half2_rn(o1.x, o1.y);
            }
        }
        if constexpr (MODE == 2) {
            ss0 += __shfl_xor_sync(0xffffffffu, ss0, 1);
            ss0 += __shfl_xor_sync(0xffffffffu, ss0, 2);
            ss1 += __shfl_xor_sync(0xffffffffu, ss1, 1);
            ss1 += __shfl_xor_sync(0xffffffffu, ss1, 2);
            if ((lane & 3) == 0) {
                if (er0 < NN) atomicAdd(&g_sumsq[er0], ss0);
                if (er1 < NN) atomicAdd(&g_sumsq[er1], ss1);
            }
        }
    }
}

// ---------------- readout + latent + rank-1 vector v (single block, 128 threads) ----------------
__global__ void small_kernel(const float* __restrict__ Whr, const float* __restrict__ bhr,
                             const float* __restrict__ Wrh, const float* __restrict__ brh,
                             const float* __restrict__ Wmu, const float* __restrict__ bmu,
                             const float* __restrict__ Wsig, const float* __restrict__ bsig,
                             const float* __restrict__ zeps, const float* __restrict__ Wh2) {
    __shared__ float sm[128], rg[128], hr[128], shz[64], zz[64];
    int t = threadIdx.x;
    sm[t] = g_colsum[t] * (1.0f / NN);
    g_colsum[t] = 0.f;                            // restore for next call
    __syncthreads();
    float acc = bhr[t];
    for (int k = 0; k < 128; k++) acc = fmaf(sm[k], Whr[k * 128 + t], acc);
    rg[t] = acc;
    __syncthreads();
    acc = brh[t];
    for (int k = 0; k < 128; k++) acc = fmaf(rg[k], Wrh[k * 128 + t], acc);
    hr[t] = fmaxf(acc, 0.f);
    __syncthreads();
    if (t < 64) {
        float mu = bmu[t], sg = bsig[t];
        for (int k = 0; k < 128; k++) {
            mu = fmaf(hr[k], Wmu[k * 64 + t], mu);
            sg = fmaf(hr[k], Wsig[k * 64 + t], sg);
        }
        float sig = 0.1f + 0.9f / (1.f + expf(-sg));
        float z = mu + sig * zeps[t];
        g_small[t] = z;
        shz[t] = z;
        zz[t] = z * z;
    }
    __syncthreads();
    if (t == 0) {
        float s = 0.f;
        for (int k = 0; k < 64; k++) s += zz[k];
        g_small[64] = s;
    }
    for (int n = t; n < 192; n += 128) {
        float a = 0.f;
        for (int j = 0; j < 64; j++) a = fmaf(shz[j], __ldg(Wh2 + (size_t)(128 + j) * 192 + n), a);
        g_v[n] = a;
    }
}

// ---------------- launch ----------------
extern "C" void kernel_launch(void* const* d_in, const int* in_sizes, int n_in,
                              void* d_out, int out_size) {
    const float* x    = (const float*)d_in[0];
    const float* ylab = (const float*)d_in[1];
    const int*   ei   = (const int*)d_in[2];
    const float* ew   = (const float*)d_in[3];
    const void*  nl   = d_in[4];
    const float* dmask= (const float*)d_in[5];
    const float* ug   = (const float*)d_in[6];
    const float* zeps = (const float*)d_in[7];
    const float* Wg1  = (const float*)d_in[8];
    const float* bg1  = (const float*)d_in[9];
    const float* Wg2  = (const float*)d_in[10];
    const float* bg2  = (const float*)d_in[11];
    const float* Wxy  = (const float*)d_in[12];
    const float* bxy  = (const float*)d_in[13];
    const float* Whr  = (const float*)d_in[14];
    const float* bhr  = (const float*)d_in[15];
    const float* Wrh  = (const float*)d_in[16];
    const float* brh  = (const float*)d_in[17];
    const float* Wmu  = (const float*)d_in[18];
    const float* bmu  = (const float*)d_in[19];
    const float* Wsig = (const float*)d_in[20];
    const float* bsig = (const float*)d_in[21];
    const float* Wxh  = (const float*)d_in[22];
    const float* bxh  = (const float*)d_in[23];
    const float* Wh2  = (const float*)d_in[24];
    const float* bh2  = (const float*)d_in[25];
    const float* Why  = (const float*)d_in[26];
    const float* bhy  = (const float*)d_in[27];
    float* out = (float*)d_out;

    __half *xg16, *hemb, *q16, *y16, *h16, *x16, *xd16, *t2, *h2, *w16;
    uint32_t *Wg1p, *Wg2p, *Wxyp, *Wxhp, *Wh2p, *Whyp;
    cudaGetSymbolAddress((void**)&xg16, g_xg16);
    cudaGetSymbolAddress((void**)&hemb, g_hemb);
    cudaGetSymbolAddress((void**)&q16,  g_q16);
    cudaGetSymbolAddress((void**)&y16,  g_y16);
    cudaGetSymbolAddress((void**)&h16,  g_h16);
    cudaGetSymbolAddress((void**)&x16,  g_x16);
    cudaGetSymbolAddress((void**)&xd16, g_xd16);
    cudaGetSymbolAddress((void**)&t2,   g_t2);
    cudaGetSymbolAddress((void**)&h2,   g_h2);
    cudaGetSymbolAddress((void**)&w16,  g_w16);
    cudaGetSymbolAddress((void**)&Wg1p, g_Wg1p);
    cudaGetSymbolAddress((void**)&Wg2p, g_Wg2p);
    cudaGetSymbolAddress((void**)&Wxyp, g_Wxyp);
    cudaGetSymbolAddress((void**)&Wxhp, g_Wxhp);
    cudaGetSymbolAddress((void**)&Wh2p, g_Wh2p);
    cudaGetSymbolAddress((void**)&Whyp, g_Whyp);

    const int TB = 256;
    const int gN    = (NN + TB - 1) / TB;
    const int gWarp = (NN * 32 + TB - 1) / TB;   // 12500
    const int GM    = (NN + 127) / 128;
    const int SCB   = (NE + TB - 1) / TB;

    mega1_kernel<<<MEGA1_GRID, TB>>>(ei, x, dmask, Wxh, Wg1, Wg2, Wxy, Wh2, Why,
                                     (const unsigned*)nl);
    scan_all<<<NSCAN, 1024>>>();
    // MEGA2: decoder pre-GEMM + encoder xg GEMM + CSR scatter in one launch
    gemm_tc<128, 128, 64, 2, true, false, false, true, true><<<GM * 4 + SCB, TB>>>(
        xd16, nullptr, Wxhp, bxh, nullptr, h16, ei, ew, x16, Wg1p, xg16);

    // encoder GCN: hemb = relu(spmm(xg16) + bg1)
    spmm_kernel<128, __half, __half, true><<<gWarp, TB>>>(xg16, hemb, bg1);
    gemm_tc<128,  32, 32, 0, false, false, false, true, false><<<dim3(GM, 1), TB>>>(
        hemb, nullptr, Wg2p, nullptr, nullptr, q16, nullptr, nullptr, nullptr, nullptr, nullptr);
    spmm_gumbel_kernel<<<gWarp, TB>>>(q16, bg2, ug, ylab, nl);

    // encoder head: colsum of relu([hemb|y] @ Wxy + bxy)
    gemm_tc<160, 128, 64, 1, true, false, false, false, false><<<dim3(GM, 2), TB>>>(
        hemb, y16, Wxyp, bxy, nullptr, nullptr, nullptr, nullptr, nullptr, nullptr, nullptr);
    small_kernel<<<1, 128>>>(Whr, bhr, Wrh, brh, Wmu, bmu, Wsig, bsig, zeps, Wh2);

    // decoder
    spmm128s_kernel<<<gWarp, TB>>>(h16, t2);
    gemm_tc<128, 192, 64, 0, true, true,  false, true, false><<<dim3(GM, 3), TB>>>(
        t2, nullptr, Wh2p, bh2, nullptr, h2, nullptr, nullptr, nullptr, nullptr, nullptr);
    gemm_tc<192,  32, 32, 0, false, false, false, true, false><<<dim3(GM, 1), TB>>>(
        h2, nullptr, Whyp, nullptr, nullptr, w16, nullptr, nullptr, nullptr, nullptr, nullptr);
    spmm32_final_kernel<<<gWarp + gN, TB>>>(w16, out, bhy);
}

// round 17
// speedup vs baseline: 1.0514x; 1.0514x over previous
#include <cuda_runtime.h>
#include <cuda_bf16.h>
#include <cuda_fp16.h>
#include <cstdint>

#define NN 100000
#define NE 1600000
#define NSCAN 98   // (NN + 1023) / 1024

// ---------------- scratch (__device__ globals; allocations are forbidden) ----------------
// Zero-initialized at module load; kernels restore the zero-state of
// g_cnt / g_colsum / g_sumsq / g_nlraw / g_scnt / g_flag / g_m1cnt each call.
__device__ __align__(256) __half g_xg16[NN * 128];
__device__ __align__(256) __half g_hemb[NN * 128];
__device__ __align__(256) __half g_q16 [NN * 32];
__device__ __align__(256) __half g_y16 [NN * 32];
__device__ __align__(256) __half g_h16 [NN * 128];
__device__ __align__(256) __half g_x16 [NN * 128];
__device__ __align__(256) __half g_xd16[NN * 128];
__device__ __align__(256) __half g_t2  [NN * 128];
__device__ __align__(256) __half g_h2  [NN * 192];
__device__ __align__(256) __half g_w16 [NN * 32];
__device__ __align__(256) float  g_sumsq[NN];
__device__ __align__(256) float  g_s   [NN];
__device__ float g_colsum[128];
__device__ float g_small[80];           // z[0..63], sum(z^2) at [64]
__device__ float g_v[192];              // z @ Wh2[128:192, :]
// packed fp16 weights: Wp[k2*DOUT+n] = half2(W[2k2][n], W[2k2+1][n])
__device__ __align__(256) uint32_t g_Wxhp[64 * 128];
__device__ __align__(256) uint32_t g_Wg1p[64 * 128];
__device__ __align__(256) uint32_t g_Wg2p[64 * 32];
__device__ __align__(256) uint32_t g_Wxyp[80 * 128];
__device__ __align__(256) uint32_t g_Wh2p[64 * 192];   // only k-rows 0..127
__device__ __align__(256) uint32_t g_Whyp[96 * 32];
__device__ int   g_rowptr[NN + 1];
__device__ int   g_cnt[NN + 1];
__device__ int   g_wpos[NN];
__device__ int   g_bsum[128];
__device__ int   g_bpref[128];
__device__ int   g_scnt;
__device__ int   g_flag;
__device__ int   g_m1cnt;
__device__ __align__(256) int2 g_cw[NE];   // packed (col, weight-bits)
__device__ int   g_nlraw;

// ---------------- MEGA1: hist + cvt_xd + weight-pack + detect_nl ----------------
__device__ __forceinline__ void wp_seg(const float* __restrict__ W, uint32_t* __restrict__ Wp,
                                       int idx, int DOUT) {
    int k2 = idx / DOUT, n = idx % DOUT;
    __half2 h = __floats2half2_rn(__ldg(W + (size_t)(2 * k2) * DOUT + n),
                                  __ldg(W + (size_t)(2 * k2 + 1) * DOUT + n));
    Wp[idx] = *reinterpret_cast<uint32_t*>(&h);
}

#define MEGA1_HB 6250
#define MEGA1_CB 12500
#define MEGA1_WB 172
#define MEGA1_DB 98
#define MEGA1_GRID (MEGA1_HB + MEGA1_CB + MEGA1_WB + MEGA1_DB)

__global__ void __launch_bounds__(256) mega1_kernel(const int* __restrict__ ei,
                                                    const float* __restrict__ x,
                                                    const float* __restrict__ dm,
                                                    const float* __restrict__ Wxh,
                                                    const float* __restrict__ Wg1,
                                                    const float* __restrict__ Wg2,
                                                    const float* __restrict__ Wxy,
                                                    const float* __restrict__ Wh2,
                                                    const float* __restrict__ Why,
                                                    const unsigned* __restrict__ nl) {
    int bid = blockIdx.x, tid = threadIdx.x;
    if (bid < MEGA1_HB) {                       // histogram
        int e = bid * 256 + tid;
        if (e < NE) atomicAdd(&g_cnt[ei[e]], 1);
        return;
    }
    bid -= MEGA1_HB;
    if (bid < MEGA1_CB) {                       // x / x*dmask -> fp16
        int i = bid * 256 + tid;
        float4 v = __ldg(reinterpret_cast<const float4*>(x) + i);
        float4 m = __ldg(reinterpret_cast<const float4*>(dm) + i);
        __half2 a = __floats2half2_rn(v.x, v.y);
        __half2 b = __floats2half2_rn(v.z, v.w);
        uint2 o;
        o.x = *reinterpret_cast<uint32_t*>(&a);
        o.y = *reinterpret_cast<uint32_t*>(&b);
        reinterpret_cast<uint2*>(g_x16)[i] = o;
        __half2 c = __floats2half2_rn(v.x * m.x, v.y * m.y);
        __half2 d = __floats2half2_rn(v.z * m.z, v.w * m.w);
        uint2 od;
        od.x = *reinterpret_cast<uint32_t*>(&c);
        od.y = *reinterpret_cast<uint32_t*>(&d);
        reinterpret_cast<uint2*>(g_xd16)[i] = od;
        return;
    }
    bid -= MEGA1_CB;
    if (bid < MEGA1_WB) {                       // weight packing, 6 segments
        int i = bid * 256 + tid;
        if (i < 8192)       wp_seg(Wxh, g_Wxhp, i, 128);
        else if (i < 16384) wp_seg(Wg1, g_Wg1p, i - 8192, 128);
        else if (i < 18432) wp_seg(Wg2, g_Wg2p, i - 16384, 32);
        else if (i < 28672) wp_seg(Wxy, g_Wxyp, i - 18432, 128);
        else if (i < 40960) wp_seg(Wh2, g_Wh2p, i - 28672, 192);
        else if (i < 44032) wp_seg(Why, g_Whyp, i - 40960, 32);
        return;
    }
    bid -= MEGA1_WB;
    {                                           // non_label dtype detect
        int i = bid * 256 + tid;
        int f = 0;
        if (i < NN / 4) {
            unsigned v = nl[i];
            if (v == 0x00003F80u || v == 0x3F803F80u) f = 4;
            else if (v == 0x3F800000u) f = 2;
            else if (v > 1u) f = 1;
        }
        if (f) atomicOr(&g_nlraw, f);
    }
}

// ---------------- CSR scan (single kernel; all 98 blocks wave-1 resident) ----------------
__global__ void __launch_bounds__(1024) scan_all() {
    __shared__ int wsum[32];
    __shared__ int pr[128];
    __shared__ int slast;
    int tid = threadIdx.x;
    int lane = tid & 31, wid = tid >> 5;
    int i = blockIdx.x * 1024 + tid;
    int v = (i < NN) ? g_cnt[i] : 0;
    if (i < NN) g_cnt[i] = 0;                 // restore for next call
    int xv = v;
#pragma unroll
    for (int o = 1; o < 32; o <<= 1) {
        int t = __shfl_up_sync(0xffffffffu, xv, o);
        if (lane >= o) xv += t;
    }
    if (lane == 31) wsum[wid] = xv;
    __syncthreads();
    if (wid == 0) {
        int w = wsum[lane];
#pragma unroll
        for (int o = 1; o < 32; o <<= 1) {
            int t = __shfl_up_sync(0xffffffffu, w, o);
            if (lane >= o) w += t;
        }
        wsum[lane] = w;
    }
    __syncthreads();
    int incl = xv + (wid ? wsum[wid - 1] : 0);
    if (tid == 1023) {
        g_bsum[blockIdx.x] = incl;
        __threadfence();
        int old = atomicAdd(&g_scnt, 1);
        slast = (old == NSCAN - 1);
    }
    __syncthreads();
    if (slast) {                               // block-uniform branch
        __threadfence();
        if (tid < 128) pr[tid] = (tid < NSCAN) ? ((volatile int*)g_bsum)[tid] : 0;
        __syncthreads();
#pragma unroll
        for (int o = 1; o < 128; o <<= 1) {
            int t = (tid < 128 && tid >= o) ? pr[tid - o] : 0;
            __syncthreads();
            if (tid < 128) pr[tid] += t;
            __syncthreads();
        }
        if (tid < NSCAN) g_bpref[tid] = tid ? pr[tid - 1] : 0;   // exclusive
        __threadfence();
        if (tid == 0) atomicExch(&g_flag, 1);
        __syncthreads();
    } else {
        if (tid == 0) { while (atomicAdd(&g_flag, 0) == 0) {} }
        __syncthreads();
        __threadfence();
    }
    int ex = incl - v + g_bpref[blockIdx.x];
    if (i < NN) {
        g_rowptr[i] = ex;
        g_wpos[i] = ex;
    }
    if (i == 0) g_rowptr[NN] = NE;
}

// ---------------- SPMM: warp per row, atomic-free (FROZEN simple loops) ----------------
// BR: fuse out = relu(acc + bias) (D=128 fp16 path only)
template<int D, typename T, typename OT, bool BR>
__global__ void __launch_bounds__(256) spmm_kernel(const T* __restrict__ h,
                                                   OT* __restrict__ out,
                                                   const float* __restrict__ bias) {
    int row = (blockIdx.x * blockDim.x + threadIdx.x) >> 5;
    if (row >= NN) return;
    int lane = threadIdx.x & 31;
    int s = g_rowptr[row], e = g_rowptr[row + 1];

    if constexpr (D == 32) {
        float acc = 0.f;
        for (; s < e; ++s) {
            int2 cw = __ldg(&g_cw[s]);
            float w = __int_as_float(cw.y);
            float v;
            if constexpr (sizeof(T) == 2) v = __half2float(__ldg((const __half*)h + (size_t)cw.x * 32 + lane));
            else                          v = __ldg((const float*)h + (size_t)cw.x * 32 + lane);
            acc = fmaf(w, v, acc);
        }
        ((float*)out)[(size_t)row * 32 + lane] = acc + (bias ? bias[lane] : 0.f);
    } else { // D == 128, fp16 -> fp16
        float4 a = make_float4(0.f, 0.f, 0.f, 0.f);
        for (; s < e; ++s) {
            int2 cw = __ldg(&g_cw[s]);
            float w = __int_as_float(cw.y);
            uint2 raw = __ldg(reinterpret_cast<const uint2*>((const __half*)h + (size_t)cw.x * 128) + lane);
            float2 f0 = __half22float2(*reinterpret_cast<__half2*>(&raw.x));
            float2 f1 = __half22float2(*reinterpret_cast<__half2*>(&raw.y));
            a.x = fmaf(w, f0.x, a.x); a.y = fmaf(w, f0.y, a.y);
            a.z = fmaf(w, f1.x, a.z); a.w = fmaf(w, f1.y, a.w);
        }
        if constexpr (BR) {
            float4 b = __ldg(reinterpret_cast<const float4*>(bias) + lane);
            a.x = fmaxf(a.x + b.x, 0.f); a.y = fmaxf(a.y + b.y, 0.f);
            a.z = fmaxf(a.z + b.z, 0.f); a.w = fmaxf(a.w + b.w, 0.f);
        }
        __half2 o0 = __floats2half2_rn(a.x, a.y);
        __half2 o1 = __floats2half2_rn(a.z, a.w);
        uint2 ov;
        ov.x = *reinterpret_cast<uint32_t*>(&o0);
        ov.y = *reinterpret_cast<uint32_t*>(&o1);
        reinterpret_cast<uint2*>((__half*)out + (size_t)row * 128)[lane] = ov;
    }
}

// SPMM D=128 over UNNORMALIZED h16, per-edge inv = rsqrt(sumsq+|z|^2), rank-1 scalar channel
__global__ void __launch_bounds__(256) spmm128s_kernel(const __half* __restrict__ h,
                                                       __half* __restrict__ out) {
    int row = (blockIdx.x * blockDim.x + threadIdx.x) >> 5;
    if (row >= NN) return;
    int lane = threadIdx.x & 31;
    float sz = g_small[64];
    int s = g_rowptr[row], e = g_rowptr[row + 1];
    float4 a = make_float4(0.f, 0.f, 0.f, 0.f);
    float sacc = 0.f;
    for (; s < e; ++s) {
        int2 cw = __ldg(&g_cw[s]);
        float wi = __int_as_float(cw.y) * rsqrtf(__ldg(g_sumsq + cw.x) + sz);
        uint2 raw = __ldg(reinterpret_cast<const uint2*>(h + (size_t)cw.x * 128) + lane);
        sacc += wi;
        float2 f0 = __half22float2(*reinterpret_cast<__half2*>(&raw.x));
        float2 f1 = __half22float2(*reinterpret_cast<__half2*>(&raw.y));
        a.x = fmaf(wi, f0.x, a.x); a.y = fmaf(wi, f0.y, a.y);
        a.z = fmaf(wi, f1.x, a.z); a.w = fmaf(wi, f1.y, a.w);
    }
    __half2 o0 = __floats2half2_rn(a.x, a.y);
    __half2 o1 = __floats2half2_rn(a.z, a.w);
    uint2 ov;
    ov.x = *reinterpret_cast<uint32_t*>(&o0);
    ov.y = *reinterpret_cast<uint32_t*>(&o1);
    reinterpret_cast<uint2*>(out + (size_t)row * 128)[lane] = ov;
    if (lane == 0) g_s[row] = sacc;
}

// SPMM D=32 over q16 fused with gumbel softmax(hard) + label select -> g_y16
__global__ void __launch_bounds__(256) spmm_gumbel_kernel(const __half* __restrict__ q16,
                                                          const float* __restrict__ bg2,
                                                          const float* __restrict__ ug,
                                                          const float* __restrict__ ylab,
                                                          const void* __restrict__ nl) {
    int row = (blockIdx.x * blockDim.x + threadIdx.x) >> 5;
    if (row >= NN) return;
    int lane = threadIdx.x & 31;
    int s = g_rowptr[row], e = g_rowptr[row + 1];
    float acc = 0.f;
    for (; s < e; ++s) {
        int2 cw = __ldg(&g_cw[s]);
        acc = fmaf(__int_as_float(cw.y),
                   __half2float(__ldg(q16 + (size_t)cw.x * 32 + lane)), acc);
    }
    float l = acc + __ldg(bg2 + lane);
    float u = __ldg(ug + (size_t)row * 32 + lane);
    float gg = -logf(-logf(u + 1e-10f) + 1e-10f);
    float t = l + gg;
    float m = t;
#pragma unroll
    for (int o = 16; o; o >>= 1) m = fmaxf(m, __shfl_xor_sync(0xffffffffu, m, o));
    unsigned ball = __ballot_sync(0xffffffffu, t == m);
    int amax = __ffs(ball) - 1;
    float ex = expf(t - m);
    float ssum = ex;
#pragma unroll
    for (int o = 16; o; o >>= 1) ssum += __shfl_xor_sync(0xffffffffu, ssum, o);
    float soft = ex / ssum;
    float hard = (lane == amax) ? 1.f : 0.f;
    float ygum = (hard + soft) - soft;
    int raw = g_nlraw;
    bool isnl;
    if (raw & 4)      isnl = __bfloat162float(((const __nv_bfloat16*)nl)[row]) != 0.f;
    else if (raw & 2) isnl = ((const float*)nl)[row] != 0.f;
    else if (raw & 1) isnl = ((const unsigned char*)nl)[row] != 0;
    else              isnl = ((const int*)nl)[row] != 0;
    g_y16[row * 32 + lane] = __float2half(isnl ? ygum : __ldg(ylab + (size_t)row * 32 + lane));
}

// Final SPMM D=32 -> d_out, trailing blocks restore zero-state globals
__global__ void __launch_bounds__(256) spmm32_final_kernel(const __half* __restrict__ h,
                                                           float* __restrict__ out,
                                                           const float* __restrict__ bias) {
    const int SPB = (NN * 32) / 256;   // 12500 spmm blocks
    if (blockIdx.x >= SPB) {
        int zi = (blockIdx.x - SPB) * 256 + threadIdx.x;
        if (zi < NN) g_sumsq[zi] = 0.f;
        if (zi == 0) { g_nlraw = 0; g_scnt = 0; g_flag = 0; g_m1cnt = 0; }
        return;
    }
    int row = (blockIdx.x * blockDim.x + threadIdx.x) >> 5;
    if (row >= NN) return;
    int lane = threadIdx.x & 31;
    int s = g_rowptr[row], e = g_rowptr[row + 1];
    float acc = 0.f;
    for (; s < e; ++s) {
        int2 cw = __ldg(&g_cw[s]);
        acc = fmaf(__int_as_float(cw.y),
                   __half2float(__ldg(h + (size_t)cw.x * 32 + lane)), acc);
    }
    out[(size_t)row * 32 + lane] = acc + __ldg(bias + lane);
}

// ---------------- small-work (readout + latent + rank-1 v), 256-thread block ----------------
__device__ void small_work(int t,
                           const float* __restrict__ Whr, const float* __restrict__ bhr,
                           const float* __restrict__ Wrh, const float* __restrict__ brh,
                           const float* __restrict__ Wmu, const float* __restrict__ bmu,
                           const float* __restrict__ Wsig, const float* __restrict__ bsig,
                           const float* __restrict__ zeps, const float* __restrict__ Wh2) {
    __shared__ float sm[128], rg[128], hr[128], shz[64], zz[64];
    if (t < 128) {
        sm[t] = g_colsum[t] * (1.0f / NN);
        g_colsum[t] = 0.f;                       // restore for next call
    }
    __syncthreads();
    if (t < 128) {
        float acc = bhr[t];
        for (int k = 0; k < 128; k++) acc = fmaf(sm[k], Whr[k * 128 + t], acc);
        rg[t] = acc;
    }
    __syncthreads();
    if (t < 128) {
        float acc = brh[t];
        for (int k = 0; k < 128; k++) acc = fmaf(rg[k], Wrh[k * 128 + t], acc);
        hr[t] = fmaxf(acc, 0.f);
    }
    __syncthreads();
    if (t < 64) {
        float mu = bmu[t], sg = bsig[t];
        for (int k = 0; k < 128; k++) {
            mu = fmaf(hr[k], Wmu[k * 64 + t], mu);
            sg = fmaf(hr[k], Wsig[k * 64 + t], sg);
        }
        float sig = 0.1f + 0.9f / (1.f + expf(-sg));
        float z = mu + sig * zeps[t];
        g_small[t] = z;
        shz[t] = z;
        zz[t] = z * z;
    }
    __syncthreads();
    if (t == 0) {
        float s = 0.f;
        for (int k = 0; k < 64; k++) s += zz[k];
        g_small[64] = s;
    }
    if (t < 128) {
        for (int n = t; n < 192; n += 128) {
            float a = 0.f;
            for (int j = 0; j < 64; j++) a = fmaf(shz[j], __ldg(Wh2 + (size_t)(128 + j) * 192 + n), a);
            g_v[n] = a;
        }
    }
}

// ---------------- tensor-core GEMM (full-W preload, per-warp A pipeline) ----------------
__device__ __forceinline__ void mma_f16(float* d, const uint32_t* a, const uint32_t* b) {
    asm volatile(
        "mma.sync.aligned.m16n8k16.row.col.f32.f16.f16.f32 "
        "{%0,%1,%2,%3},{%4,%5,%6,%7},{%8,%9},{%0,%1,%2,%3};"
        : "+f"(d[0]), "+f"(d[1]), "+f"(d[2]), "+f"(d[3])
        : "r"(a[0]), "r"(a[1]), "r"(a[2]), "r"(a[3]), "r"(b[0]), "r"(b[1]));
}
__device__ __forceinline__ void cpa16(uint32_t dst, const void* src, int sz) {
    asm volatile("cp.async.ca.shared.global [%0], [%1], 16, %2;" :: "r"(dst), "l"(src), "r"(sz));
}

// MODE 0: C = act(A1 @ W + b); MODE 1: relu + column sums (A=[A1 128 | A2 32])
//         + FUSED small_work in last-done block;
// MODE 2: MODE 0 + row sum-of-squares atomics
// RANK1: acc += g_s[row]*g_v[col] before bias/relu
// SCAT:  block ranges = [primary GEMM | secondary GEMM (A1b@Wgb->C16b plain) | edge scatter]
template<int DIN, int DOUT, int BN, int MODE, bool RELU, bool RANK1, bool W32, bool W16, bool SCAT>
__global__ void __launch_bounds__(256) gemm_tc(const __half* __restrict__ A1,
                                               const __half* __restrict__ A2,
                                               const uint32_t* __restrict__ Wg,
                                               const float* __restrict__ bias,
                                               float* __restrict__ C,
                                               __half* __restrict__ C16,
                                               const int* __restrict__ ei,
                                               const float* __restrict__ ew,
                                               const __half* __restrict__ A1b,
                                               const uint32_t* __restrict__ Wgb,
                                               __half* __restrict__ C16b,
                                               const float* __restrict__ sWhr,
                                               const float* __restrict__ sbhr,
                                               const float* __restrict__ sWrh,
                                               const float* __restrict__ sbrh,
                                               const float* __restrict__ sWmu,
                                               const float* __restrict__ sbmu,
                                               const float* __restrict__ sWsig,
                                               const float* __restrict__ sbsig,
                                               const float* __restrict__ szeps,
                                               const float* __restrict__ sWh2) {
    constexpr int GMc = (NN + 127) / 128;
    constexpr int KC = 32;
    constexpr int AST2 = 20;
    constexpr int WST = BN + 8;
    constexpr int NT = BN / 8;
    constexpr int NCH = DIN / KC;
    constexpr int NK2 = DIN / 2;

    const int tid = threadIdx.x;
    int bx, by;
    bool sec = false;
    if constexpr (SCAT) {
        constexpr int GB = GMc * (DOUT / BN);
        if (blockIdx.x >= 2 * GB) {
            int e = (blockIdx.x - 2 * GB) * 256 + tid;
            if (e < NE) {
                int r = __ldg(ei + e);
                int p = atomicAdd(&g_wpos[r], 1);
                g_cw[p] = make_int2(__ldg(ei + NE + e), __float_as_int(__ldg(ew + e)));
            }
            return;
        }
        int b = blockIdx.x;
        if (b >= GB) { sec = true; b -= GB; }
        bx = b % GMc;
        by = b / GMc;
    } else {
        bx = blockIdx.x;
        by = blockIdx.y;
    }

    __shared__ uint32_t As2[2][128][AST2];
    __shared__ uint32_t Ws[NK2][WST];
    __shared__ float s_cs[(MODE == 1) ? BN : 1];

    const int wid  = tid >> 5;
    const int lane = tid & 31;
    const int row0 = bx * 128;
    const int n0   = by * BN;

    const __half* Ap = (SCAT && sec) ? A1b : A1;
    const uint32_t* Wp = (SCAT && sec) ? Wgb : Wg;

    if constexpr (MODE == 1) { if (tid < BN) s_cs[tid] = 0.f; }

    constexpr int W4 = NK2 * (BN / 4);
    for (int i = tid; i < W4; i += 256) {
        int k2 = i / (BN / 4);
        int c4 = (i % (BN / 4)) * 4;
        cpa16((uint32_t)__cvta_generic_to_shared(&Ws[k2][c4]),
              Wp + (size_t)k2 * DOUT + n0 + c4, 16);
    }
    asm volatile("cp.async.commit_group;");

    auto load_A = [&](int buf, int kc) {
#pragma unroll
        for (int j = 0; j < 2; j++) {
            int sid = lane + j * 32;
            int r = wid * 16 + (sid >> 2);
            int seg = sid & 3;
            int gr = row0 + r;
            int sz = (gr < NN) ? 16 : 0;
            int grc = (gr < NN) ? gr : (NN - 1);
            int gk = kc + seg * 8;
            const __half* src;
            if constexpr (MODE == 1) {
                src = (gk < 128) ? (Ap + (size_t)grc * 128 + gk)
                                 : (A2 + (size_t)grc * 32 + (gk - 128));
            } else {
                src = Ap + (size_t)grc * DIN + gk;
            }
            cpa16((uint32_t)__cvta_generic_to_shared(&As2[buf][r][seg * 4]), src, sz);
        }
        asm volatile("cp.async.commit_group;");
    };

    float acc[NT][4];
#pragma unroll
    for (int t = 0; t < NT; t++)
#pragma unroll
        for (int j = 0; j < 4; j++) acc[t][j] = 0.f;

    load_A(0, 0);
    asm volatile("cp.async.wait_group 1;");
    __syncthreads();

#pragma unroll
    for (int c = 0; c < NCH; c++) {
        if (c + 1 < NCH) {
            load_A((c + 1) & 1, (c + 1) * KC);
            asm volatile("cp.async.wait_group 1;");
        } else {
            asm volatile("cp.async.wait_group 0;");
        }
        __syncwarp();
        const int buf = c & 1;
#pragma unroll
        for (int s = 0; s < 2; s++) {
            int k2o = s * 8;
            int m0 = wid * 16;
            int r = lane >> 2, q = lane & 3, bp = lane >> 2;
            uint32_t a[4];
            a[0] = As2[buf][m0 + r][k2o + q];
            a[1] = As2[buf][m0 + r + 8][k2o + q];
            a[2] = As2[buf][m0 + r][k2o + 4 + q];
            a[3] = As2[buf][m0 + r + 8][k2o + 4 + q];
#pragma unroll
            for (int t = 0; t < NT; t++) {
                uint32_t b[2];
                b[0] = Ws[c * 16 + k2o + q][t * 8 + bp];
                b[1] = Ws[c * 16 + k2o + 4 + q][t * 8 + bp];
                mma_f16(acc[t], a, b);
            }
        }
    }

    const int er0 = row0 + wid * 16 + (lane >> 2);
    const int er1 = er0 + 8;

    if (SCAT && sec) {     // secondary GEMM: plain fp16 store, no bias/relu
#pragma unroll
        for (int t = 0; t < NT; t++) {
            int gc = n0 + t * 8 + 2 * (lane & 3);
            if (er0 < NN)
                *reinterpret_cast<__half2*>(&C16b[(size_t)er0 * DOUT + gc]) =
                    __floats2half2_rn(acc[t][0], acc[t][1]);
            if (er1 < NN)
                *reinterpret_cast<__half2*>(&C16b[(size_t)er1 * DOUT + gc]) =
                    __floats2half2_rn(acc[t][2], acc[t][3]);
        }
        return;
    }

    if constexpr (MODE == 1) {
#pragma unroll
        for (int t = 0; t < NT; t++) {
            int gc = n0 + t * 8 + 2 * (lane & 3);
            float b0 = __ldg(bias + gc), b1 = __ldg(bias + gc + 1);
            float v0 = 0.f, v1 = 0.f;
            if (er0 < NN) { v0 += fmaxf(acc[t][0] + b0, 0.f); v1 += fmaxf(acc[t][1] + b1, 0.f); }
            if (er1 < NN) { v0 += fmaxf(acc[t][2] + b0, 0.f); v1 += fmaxf(acc[t][3] + b1, 0.f); }
#pragma unroll
            for (int o = 4; o < 32; o <<= 1) {
                v0 += __shfl_xor_sync(0xffffffffu, v0, o);
                v1 += __shfl_xor_sync(0xffffffffu, v1, o);
            }
            if ((lane >> 2) == 0) {
                atomicAdd(&s_cs[t * 8 + 2 * (lane & 3)], v0);
                atomicAdd(&s_cs[t * 8 + 2 * (lane & 3) + 1], v1);
            }
        }
        __syncthreads();
        if (tid < BN) atomicAdd(&g_colsum[n0 + tid], s_cs[tid]);
        // last-done block computes the readout/latent chain (fence+counter pattern)
        __shared__ int s_last;
        __threadfence();
        __syncthreads();
        if (tid == 0) {
            int old = atomicAdd(&g_m1cnt, 1);
            s_last = (old == GMc * (DOUT / BN) - 1);
        }
        __syncthreads();
        if (s_last) {
            __threadfence();
            small_work(tid, sWhr, sbhr, sWrh, sbrh, sWmu, sbmu, sWsig, sbsig, szeps, sWh2);
            if (tid == 0) g_m1cnt = 0;           // restore for next call
        }
    } else {
        float s0 = 0.f, s1 = 0.f;
        if constexpr (RANK1) {
            if (er0 < NN) s0 = __ldg(g_s + er0);
            if (er1 < NN) s1 = __ldg(g_s + er1);
        }
        float ss0 = 0.f, ss1 = 0.f;
#pragma unroll
        for (int t = 0; t < NT; t++) {
            int gc = n0 + t * 8 + 2 * (lane & 3);
            float b0 = bias ? __ldg(bias + gc) : 0.f;
            float b1 = bias ? __ldg(bias + gc + 1) : 0.f;
            float2 o0 = make_float2(acc[t][0] + b0, acc[t][1] + b1);
            float2 o1 = make_float2(acc[t][2] + b0, acc[t][3] + b1);
            if constexpr (RANK1) {
                float v0 = __ldg(g_v + gc), v1 = __ldg(g_v + gc + 1);
                o0.x = fmaf(s0, v0, o0.x); o0.y = fmaf(s0, v1, o0.y);
                o1.x = fmaf(s1, v0, o1.x); o1.y = fmaf(s1, v1, o1.y);
            }
            if (RELU) {
                o0.x = fmaxf(o0.x, 0.f); o0.y = fmaxf(o0.y, 0.f);
                o1.x = fmaxf(o1.x, 0.f); o1.y = fmaxf(o1.y, 0.f);
            }
            if constexpr (MODE == 2) {
                ss0 = fmaf(o0.x, o0.x, fmaf(o0.y, o0.y, ss0));
                ss1 = fmaf(o1.x, o1.x, fmaf(o1.y, o1.y, ss1));
            }
            if (er0 < NN) {
                if (W32) *reinterpret_cast<float2*>(&C[(size_t)er0 * DOUT + gc]) = o0;
                if (W16) *reinterpret_cast<__half2*>(&C16[(size_t)er0 * DOUT + gc]) = __floats2half2_rn(o0.x, o0.y);
            }
            if (er1 < NN) {
                if (W32) *reinterpret_cast<float2*>(&C[(size_t)er1 * DOUT + gc]) = o1;
                if (W16) *reinterpret_cast<__half2*>(&C16[(size_t)er1 * DOUT + gc]) = __floats2half2_rn(o1.x, o1.y);
            }
        }
        if constexpr (MODE == 2) {
            ss0 += __shfl_xor_sync(0xffffffffu, ss0, 1);
            ss0 += __shfl_xor_sync(0xffffffffu, ss0, 2);
            ss1 += __shfl_xor_sync(0xffffffffu, ss1, 1);
            ss1 += __shfl_xor_sync(0xffffffffu, ss1, 2);
            if ((lane & 3) == 0) {
                if (er0 < NN) atomicAdd(&g_sumsq[er0], ss0);
                if (er1 < NN) atomicAdd(&g_sumsq[er1], ss1);
            }
        }
    }
}

// ---------------- launch ----------------
extern "C" void kernel_launch(void* const* d_in, const int* in_sizes, int n_in,
                              void* d_out, int out_size) {
    const float* x    = (const float*)d_in[0];
    const float* ylab = (const float*)d_in[1];
    const int*   ei   = (const int*)d_in[2];
    const float* ew   = (const float*)d_in[3];
    const void*  nl   = d_in[4];
    const float* dmask= (const float*)d_in[5];
    const float* ug   = (const float*)d_in[6];
    const float* zeps = (const float*)d_in[7];
    const float* Wg1  = (const float*)d_in[8];
    const float* bg1  = (const float*)d_in[9];
    const float* Wg2  = (const float*)d_in[10];
    const float* bg2  = (const float*)d_in[11];
    const float* Wxy  = (const float*)d_in[12];
    const float* bxy  = (const float*)d_in[13];
    const float* Whr  = (const float*)d_in[14];
    const float* bhr  = (const float*)d_in[15];
    const float* Wrh  = (const float*)d_in[16];
    const float* brh  = (const float*)d_in[17];
    const float* Wmu  = (const float*)d_in[18];
    const float* bmu  = (const float*)d_in[19];
    const float* Wsig = (const float*)d_in[20];
    const float* bsig = (const float*)d_in[21];
    const float* Wxh  = (const float*)d_in[22];
    const float* bxh  = (const float*)d_in[23];
    const float* Wh2  = (const float*)d_in[24];
    const float* bh2  = (const float*)d_in[25];
    const float* Why  = (const float*)d_in[26];
    const float* bhy  = (const float*)d_in[27];
    float* out = (float*)d_out;

    __half *xg16, *hemb, *q16, *y16, *h16, *x16, *xd16, *t2, *h2, *w16;
    uint32_t *Wg1p, *Wg2p, *Wxyp, *Wxhp, *Wh2p, *Whyp;
    cudaGetSymbolAddress((void**)&xg16, g_xg16);
    cudaGetSymbolAddress((void**)&hemb, g_hemb);
    cudaGetSymbolAddress((void**)&q16,  g_q16);
    cudaGetSymbolAddress((void**)&y16,  g_y16);
    cudaGetSymbolAddress((void**)&h16,  g_h16);
    cudaGetSymbolAddress((void**)&x16,  g_x16);
    cudaGetSymbolAddress((void**)&xd16, g_xd16);
    cudaGetSymbolAddress((void**)&t2,   g_t2);
    cudaGetSymbolAddress((void**)&h2,   g_h2);
    cudaGetSymbolAddress((void**)&w16,  g_w16);
    cudaGetSymbolAddress((void**)&Wg1p, g_Wg1p);
    cudaGetSymbolAddress((void**)&Wg2p, g_Wg2p);
    cudaGetSymbolAddress((void**)&Wxyp, g_Wxyp);
    cudaGetSymbolAddress((void**)&Wxhp, g_Wxhp);
    cudaGetSymbolAddress((void**)&Wh2p, g_Wh2p);
    cudaGetSymbolAddress((void**)&Whyp, g_Whyp);

    const int TB = 256;
    const int gN    = (NN + TB - 1) / TB;
    const int gWarp = (NN * 32 + TB - 1) / TB;   // 12500
    const int GM    = (NN + 127) / 128;
    const int SCB   = (NE + TB - 1) / TB;

    mega1_kernel<<<MEGA1_GRID, TB>>>(ei, x, dmask, Wxh, Wg1, Wg2, Wxy, Wh2, Why,
                                     (const unsigned*)nl);
    scan_all<<<NSCAN, 1024>>>();
    // MEGA2: decoder pre-GEMM + encoder xg GEMM + CSR scatter in one launch
    gemm_tc<128, 128, 64, 2, true, false, false, true, true><<<GM * 4 + SCB, TB>>>(
        xd16, nullptr, Wxhp, bxh, nullptr, h16, ei, ew, x16, Wg1p, xg16,
        nullptr, nullptr, nullptr, nullptr, nullptr, nullptr, nullptr, nullptr, nullptr, nullptr);

    // encoder GCN: hemb = relu(spmm(xg16) + bg1)
    spmm_kernel<128, __half, __half, true><<<gWarp, TB>>>(xg16, hemb, bg1);
    gemm_tc<128,  32, 32, 0, false, false, false, true, false><<<dim3(GM, 1), TB>>>(
        hemb, nullptr, Wg2p, nullptr, nullptr, q16, nullptr, nullptr, nullptr, nullptr, nullptr,
        nullptr, nullptr, nullptr, nullptr, nullptr, nullptr, nullptr, nullptr, nullptr, nullptr);
    spmm_gumbel_kernel<<<gWarp, TB>>>(q16, bg2, ug, ylab, nl);

    // encoder head: colsum of relu([hemb|y] @ Wxy + bxy) + fused small_work in last block
    gemm_tc<160, 128, 64, 1, true, false, false, false, false><<<dim3(GM, 2), TB>>>(
        hemb, y16, Wxyp, bxy, nullptr, nullptr, nullptr, nullptr, nullptr, nullptr, nullptr,
        Whr, bhr, Wrh, brh, Wmu, bmu, Wsig, bsig, zeps, Wh2);

    // decoder
    spmm128s_kernel<<<gWarp, TB>>>(h16, t2);
    gemm_tc<128, 192, 64, 0, true, true,  false, true, false><<<dim3(GM, 3), TB>>>(
        t2, nullptr, Wh2p, bh2, nullptr, h2, nullptr, nullptr, nullptr, nullptr, nullptr,
        nullptr, nullptr, nullptr, nullptr, nullptr, nullptr, nullptr, nullptr, nullptr, nullptr);
    gemm_tc<192,  32, 32, 0, false, false, false, true, false><<<dim3(GM, 1), TB>>>(
        h2, nullptr, Whyp, nullptr, nullptr, w16, nullptr, nullptr, nullptr, nullptr, nullptr,
        nullptr, nullptr, nullptr, nullptr, nullptr, nullptr, nullptr, nullptr, nullptr, nullptr);
    spmm32_final_kernel<<<gWarp + gN, TB>>>(w16, out, bhy);
}